// round 5
// baseline (speedup 1.0000x reference)
#include <cuda_runtime.h>
#include <cuda_bf16.h>
#include <stdint.h>

#define N_NODES 50000
#define N_EDGES 800000
#define C_IN    256
#define C_HID   128
#define C_OUT   64

// ---------------- scratch (static device globals; no allocation) ----------------
__device__ int   g_is64;
__device__ int   g_cnt[N_NODES];
__device__ float g_dinv[N_NODES];
__device__ int   g_rowptr[N_NODES + 1];
__device__ int   g_fill[N_NODES];
__device__ int   g_srcidx[N_EDGES];
__device__ float g_norm[N_EDGES];
__device__ float g_h1[(size_t)N_NODES * C_HID];   // X @ W1
__device__ float g_a1[(size_t)N_NODES * C_HID];   // relu(aggregate(h1) + b1)
__device__ float g_h2[(size_t)N_NODES * C_OUT];   // a1 @ W2

// ---------------- edge dtype detection ----------------
// If edge_index is genuinely int64, its first entries interpreted as int64 are
// all in [0, N_NODES). If it is int32, the int64 view packs two random values
// (lo + hi*2^32) and lands far out of range. 8 probes on src + dst each.
__global__ void detect_dtype_kernel(const void* ei) {
    const long long* e64 = (const long long*)ei;
    bool ok = true;
    for (int i = 0; i < 8; i++) {
        long long s = e64[i];
        long long d = e64[N_EDGES + i];
        if (s < 0 || s >= N_NODES || d < 0 || d >= N_NODES) ok = false;
    }
    g_is64 = ok ? 1 : 0;
}

// clamped decode: even under a wrong dtype theory this can't produce an
// out-of-range index (degrades to wrong-answer, which is diagnosable).
__device__ __forceinline__ int edge_at(const void* ei, size_t idx, int is64) {
    long long v;
    if (is64) v = ((const long long*)ei)[idx];
    else      v = (long long)((const int*)ei)[idx];
    v = v < 0 ? 0 : (v >= N_NODES ? N_NODES - 1 : v);
    return (int)v;
}

// ---------------- CSR build ----------------
__global__ void zero_cnt_kernel() {
    int i = blockIdx.x * blockDim.x + threadIdx.x;
    if (i < N_NODES) g_cnt[i] = 0;
}

__global__ void count_kernel(const void* __restrict__ ei) {
    int e = blockIdx.x * blockDim.x + threadIdx.x;
    if (e < N_EDGES) {
        int d = edge_at(ei, (size_t)N_EDGES + e, g_is64);
        atomicAdd(&g_cnt[d], 1);
    }
}

__global__ void dinv_kernel() {
    int i = blockIdx.x * blockDim.x + threadIdx.x;
    if (i < N_NODES) {
        float deg = (float)g_cnt[i] + 1.0f;   // +1 for self loop
        g_dinv[i] = rsqrtf(deg);
    }
}

// single-block exclusive scan over g_cnt -> g_rowptr (also seeds g_fill)
__global__ void scan_kernel() {
    __shared__ int sums[1024];
    const int tid = threadIdx.x;
    const int CHUNK = (N_NODES + 1023) / 1024;
    int begin = tid * CHUNK;
    int end   = min(begin + CHUNK, N_NODES);
    int s = 0;
    for (int i = begin; i < end; i++) s += g_cnt[i];
    sums[tid] = s;
    __syncthreads();
    for (int off = 1; off < 1024; off <<= 1) {
        int v = 0;
        if (tid >= off) v = sums[tid - off];
        __syncthreads();
        if (tid >= off) sums[tid] += v;
        __syncthreads();
    }
    int run = (tid == 0) ? 0 : sums[tid - 1];
    for (int i = begin; i < end; i++) {
        g_rowptr[i] = run;
        g_fill[i]   = run;
        run += g_cnt[i];
    }
    if (tid == 0) g_rowptr[N_NODES] = N_EDGES;
}

__global__ void scatter_kernel(const void* __restrict__ ei) {
    int e = blockIdx.x * blockDim.x + threadIdx.x;
    if (e < N_EDGES) {
        int is64 = g_is64;
        int s = edge_at(ei, e, is64);
        int d = edge_at(ei, (size_t)N_EDGES + e, is64);
        int p = atomicAdd(&g_fill[d], 1);
        // p is in [rowptr[d], rowptr[d+1]) by construction: counts and
        // scatter use the same clamped decode.
        g_srcidx[p] = s;
        g_norm[p]   = g_dinv[s] * g_dinv[d];
    }
}

// ---------------- SGEMM (fp32, tiled) ----------------
// LAYER 0: C=g_h1 <- A_ext[x] @ B ;  LAYER 1: C=g_h2 <- g_a1 @ B
template <int BM, int BN, int BK, int TM, int TN, int LAYER>
__global__ void __launch_bounds__((BM / TM) * (BN / TN))
sgemm_kernel(const float* __restrict__ A_ext, const float* __restrict__ B,
             int M, int N, int K) {
    const float* __restrict__ A = (LAYER == 0) ? A_ext : (const float*)g_a1;
    float* __restrict__ C = (LAYER == 0) ? (float*)g_h1 : (float*)g_h2;

    constexpr int THREADS = (BM / TM) * (BN / TN);
    constexpr int NA4 = BM * BK / 4;
    constexpr int NB4 = BK * BN / 4;
    constexpr int AK4 = BK / 4;
    constexpr int BC4 = BN / 4;

    __shared__ float As[BK][BM];
    __shared__ float Bs[BK][BN];

    const int tid = threadIdx.x;
    const int block_m = blockIdx.x * BM;
    const int tcol = tid % (BN / TN);
    const int trow = tid / (BN / TN);

    float acc[TM][TN];
#pragma unroll
    for (int i = 0; i < TM; i++)
#pragma unroll
        for (int j = 0; j < TN; j++) acc[i][j] = 0.0f;

    for (int k0 = 0; k0 < K; k0 += BK) {
#pragma unroll
        for (int i = 0; i < NA4; i += THREADS) {
            int idx = i + tid;
            int row = idx / AK4;
            int k4  = idx % AK4;
            float4 v = make_float4(0.f, 0.f, 0.f, 0.f);
            int gm = block_m + row;
            if (gm < M) v = *(const float4*)&A[(size_t)gm * K + k0 + k4 * 4];
            As[k4 * 4 + 0][row] = v.x;
            As[k4 * 4 + 1][row] = v.y;
            As[k4 * 4 + 2][row] = v.z;
            As[k4 * 4 + 3][row] = v.w;
        }
#pragma unroll
        for (int i = 0; i < NB4; i += THREADS) {
            int idx = i + tid;
            if (idx < NB4) {
                int kr = idx / BC4;
                int c4 = idx % BC4;
                float4 v = *(const float4*)&B[(size_t)(k0 + kr) * N + c4 * 4];
                *(float4*)&Bs[kr][c4 * 4] = v;
            }
        }
        __syncthreads();

#pragma unroll
        for (int kk = 0; kk < BK; kk++) {
            float a[TM], b[TN];
#pragma unroll
            for (int i = 0; i < TM / 4; i++) {
                float4 t = *(const float4*)&As[kk][trow * TM + i * 4];
                a[i * 4 + 0] = t.x; a[i * 4 + 1] = t.y;
                a[i * 4 + 2] = t.z; a[i * 4 + 3] = t.w;
            }
#pragma unroll
            for (int j = 0; j < TN / 4; j++) {
                float4 t = *(const float4*)&Bs[kk][tcol * TN + j * 4];
                b[j * 4 + 0] = t.x; b[j * 4 + 1] = t.y;
                b[j * 4 + 2] = t.z; b[j * 4 + 3] = t.w;
            }
#pragma unroll
            for (int i = 0; i < TM; i++)
#pragma unroll
                for (int j = 0; j < TN; j++)
                    acc[i][j] += a[i] * b[j];
        }
        __syncthreads();
    }

#pragma unroll
    for (int i = 0; i < TM; i++) {
        int gm = block_m + trow * TM + i;
        if (gm < M) {
#pragma unroll
            for (int j4 = 0; j4 < TN / 4; j4++) {
                float4 v = make_float4(acc[i][j4 * 4 + 0], acc[i][j4 * 4 + 1],
                                       acc[i][j4 * 4 + 2], acc[i][j4 * 4 + 3]);
                *(float4*)&C[(size_t)gm * N + tcol * TN + j4 * 4] = v;
            }
        }
    }
}

// ---------------- aggregation (one warp per dst node) ----------------
__global__ void agg128_relu_kernel(const float* __restrict__ bias) {
    const float* __restrict__ h = (const float*)g_h1;
    float* __restrict__ out = (float*)g_a1;
    const int warp = blockIdx.x * (blockDim.x >> 5) + (threadIdx.x >> 5);
    const int lane = threadIdx.x & 31;
    if (warp >= N_NODES) return;

    const int start = g_rowptr[warp];
    const int end   = g_rowptr[warp + 1];

    float4 acc = make_float4(0.f, 0.f, 0.f, 0.f);
    for (int base = start; base < end; base += 32) {
        int e = base + lane;
        int s = 0; float nm = 0.f;
        if (e < end) { s = g_srcidx[e]; nm = g_norm[e]; }
        int cnt = min(32, end - base);
        for (int j = 0; j < cnt; j++) {
            int   ss = __shfl_sync(0xffffffffu, s, j);
            float nn = __shfl_sync(0xffffffffu, nm, j);
            float4 v = *(const float4*)&h[(size_t)ss * C_HID + lane * 4];
            acc.x += v.x * nn; acc.y += v.y * nn;
            acc.z += v.z * nn; acc.w += v.w * nn;
        }
    }
    float dv = g_dinv[warp];
    float sn = dv * dv;
    float4 v = *(const float4*)&h[(size_t)warp * C_HID + lane * 4];
    acc.x += v.x * sn; acc.y += v.y * sn; acc.z += v.z * sn; acc.w += v.w * sn;
    float4 b = *(const float4*)&bias[lane * 4];
    acc.x += b.x; acc.y += b.y; acc.z += b.z; acc.w += b.w;
    acc.x = fmaxf(acc.x, 0.f); acc.y = fmaxf(acc.y, 0.f);
    acc.z = fmaxf(acc.z, 0.f); acc.w = fmaxf(acc.w, 0.f);
    *(float4*)&out[(size_t)warp * C_HID + lane * 4] = acc;
}

__global__ void agg64_kernel(const float* __restrict__ bias,
                             float* __restrict__ out) {
    const float* __restrict__ h = (const float*)g_h2;
    const int warp = blockIdx.x * (blockDim.x >> 5) + (threadIdx.x >> 5);
    const int lane = threadIdx.x & 31;
    if (warp >= N_NODES) return;

    const int start = g_rowptr[warp];
    const int end   = g_rowptr[warp + 1];

    float2 acc = make_float2(0.f, 0.f);
    for (int base = start; base < end; base += 32) {
        int e = base + lane;
        int s = 0; float nm = 0.f;
        if (e < end) { s = g_srcidx[e]; nm = g_norm[e]; }
        int cnt = min(32, end - base);
        for (int j = 0; j < cnt; j++) {
            int   ss = __shfl_sync(0xffffffffu, s, j);
            float nn = __shfl_sync(0xffffffffu, nm, j);
            float2 v = *(const float2*)&h[(size_t)ss * C_OUT + lane * 2];
            acc.x += v.x * nn; acc.y += v.y * nn;
        }
    }
    float dv = g_dinv[warp];
    float sn = dv * dv;
    float2 v = *(const float2*)&h[(size_t)warp * C_OUT + lane * 2];
    acc.x += v.x * sn; acc.y += v.y * sn;
    float2 b = *(const float2*)&bias[lane * 2];
    acc.x += b.x; acc.y += b.y;
    *(float2*)&out[(size_t)warp * C_OUT + lane * 2] = acc;
}

// ---------------- launch ----------------
extern "C" void kernel_launch(void* const* d_in, const int* in_sizes, int n_in,
                              void* d_out, int out_size) {
    const float* x  = (const float*)d_in[0];
    const void*  ei = d_in[1];
    const float* W1 = (const float*)d_in[2];
    const float* b1 = (const float*)d_in[3];
    const float* W2 = (const float*)d_in[4];
    const float* b2 = (const float*)d_in[5];
    float* out = (float*)d_out;

    const int TB = 256;
    const int nodeBlocks = (N_NODES + TB - 1) / TB;
    const int edgeBlocks = (N_EDGES + TB - 1) / TB;

    detect_dtype_kernel<<<1, 1>>>(ei);
    zero_cnt_kernel<<<nodeBlocks, TB>>>();
    count_kernel<<<edgeBlocks, TB>>>(ei);
    dinv_kernel<<<nodeBlocks, TB>>>();
    scan_kernel<<<1, 1024>>>();
    scatter_kernel<<<edgeBlocks, TB>>>(ei);

    // layer 1: g_h1 = x @ W1
    {
        constexpr int BM = 128, BN = 128, BK = 16, TM = 8, TN = 8;
        int grid = (N_NODES + BM - 1) / BM;
        sgemm_kernel<BM, BN, BK, TM, TN, 0><<<grid, (BM / TM) * (BN / TN)>>>(
            x, W1, N_NODES, C_HID, C_IN);
    }
    // g_a1 = relu(aggregate(g_h1) + b1)
    {
        const int WPB = 8;
        int grid = (N_NODES + WPB - 1) / WPB;
        agg128_relu_kernel<<<grid, WPB * 32>>>(b1);
    }
    // layer 2: g_h2 = g_a1 @ W2
    {
        constexpr int BM = 128, BN = 64, BK = 16, TM = 8, TN = 4;
        int grid = (N_NODES + BM - 1) / BM;
        sgemm_kernel<BM, BN, BK, TM, TN, 1><<<grid, (BM / TM) * (BN / TN)>>>(
            nullptr, W2, N_NODES, C_OUT, C_HID);
    }
    // out = aggregate(g_h2) + b2
    {
        const int WPB = 8;
        int grid = (N_NODES + WPB - 1) / WPB;
        agg64_kernel<<<grid, WPB * 32>>>(b2, out);
    }
}